// round 2
// baseline (speedup 1.0000x reference)
#include <cuda_runtime.h>
#include <cuda_bf16.h>
#include <math.h>

// Problem constants
#define BB 4
#define NN 2048
#define CC 384
#define HH 8
#define HD 48
#define TT (BB * NN)          // 8192 tokens
#define SCALE 0.14433756729740645f  // 1/sqrt(48)

typedef unsigned long long u64;

// ---- packed f32x2 helpers (Blackwell sm_103a; ptxas never emits these) ----
__device__ __forceinline__ u64 ffma2(u64 a, u64 b, u64 c) {
    u64 d; asm("fma.rn.f32x2 %0, %1, %2, %3;" : "=l"(d) : "l"(a), "l"(b), "l"(c)); return d;
}
__device__ __forceinline__ u64 fmul2(u64 a, u64 b) {
    u64 d; asm("mul.rn.f32x2 %0, %1, %2;" : "=l"(d) : "l"(a), "l"(b)); return d;
}
__device__ __forceinline__ u64 fadd2(u64 a, u64 b) {
    u64 d; asm("add.rn.f32x2 %0, %1, %2;" : "=l"(d) : "l"(a), "l"(b)); return d;
}
__device__ __forceinline__ u64 pack2(float lo, float hi) {
    u64 r; asm("mov.b64 %0, {%1, %2};" : "=l"(r) : "f"(lo), "f"(hi)); return r;
}
__device__ __forceinline__ float2 unpack2(u64 v) {
    float lo, hi; asm("mov.b64 {%0, %1}, %2;" : "=f"(lo), "=f"(hi) : "l"(v));
    return make_float2(lo, hi);
}

// Scratch (static device globals — no runtime allocation)
__device__ float g_Q[TT * CC];
__device__ float g_K[TT * CC];
__device__ float g_V[TT * CC];
__device__ float g_X[TT * CC];

// ---------------------------------------------------------------------------
// GEMM: out[m][n] = sum_k A[m][k] * W[n][k] + bias[n]
// Tiles: BM=64, BN=64, BK=16; 256 threads; 4x4 micro-tile per thread.
// Inner product uses packed fma.rn.f32x2 (acc packed along n).
// ---------------------------------------------------------------------------
__global__ void gemm_nt_bias(const float* __restrict__ A,
                             const float* __restrict__ W,
                             const float* __restrict__ bias,
                             float* __restrict__ out)
{
    const int K = CC;
    __shared__ float As[16][68];  // [kk][row]
    __shared__ float Ws[16][68];  // [kk][col]

    int tid = threadIdx.x;          // 0..255
    int tx = tid & 15;              // column group
    int ty = tid >> 4;              // row group
    int row0 = blockIdx.y * 64;
    int col0 = blockIdx.x * 64;

    int lr = tid >> 2;              // 0..63 (row/col to load)
    int lk = (tid & 3) << 2;        // 0,4,8,12 (k offset)

    u64 acc2[4][2];
#pragma unroll
    for (int i = 0; i < 4; i++) { acc2[i][0] = 0ull; acc2[i][1] = 0ull; }

    for (int k0 = 0; k0 < K; k0 += 16) {
        float4 a = *(const float4*)(A + (size_t)(row0 + lr) * K + k0 + lk);
        float4 w = *(const float4*)(W + (size_t)(col0 + lr) * K + k0 + lk);
        __syncthreads();
        As[lk + 0][lr] = a.x; As[lk + 1][lr] = a.y;
        As[lk + 2][lr] = a.z; As[lk + 3][lr] = a.w;
        Ws[lk + 0][lr] = w.x; Ws[lk + 1][lr] = w.y;
        Ws[lk + 2][lr] = w.z; Ws[lk + 3][lr] = w.w;
        __syncthreads();

#pragma unroll
        for (int kk = 0; kk < 16; kk++) {
            float4 av = *(const float4*)&As[kk][ty * 4];
            ulonglong2 wv = *(const ulonglong2*)&Ws[kk][tx * 4];
            float ar[4] = {av.x, av.y, av.z, av.w};
#pragma unroll
            for (int i = 0; i < 4; i++) {
                u64 ai = pack2(ar[i], ar[i]);
                acc2[i][0] = ffma2(ai, wv.x, acc2[i][0]);
                acc2[i][1] = ffma2(ai, wv.y, acc2[i][1]);
            }
        }
    }

    float4 bv = *(const float4*)(bias + col0 + tx * 4);
#pragma unroll
    for (int i = 0; i < 4; i++) {
        float2 p0 = unpack2(acc2[i][0]);
        float2 p1 = unpack2(acc2[i][1]);
        float4 r;
        r.x = p0.x + bv.x;
        r.y = p0.y + bv.y;
        r.z = p1.x + bv.z;
        r.w = p1.y + bv.w;
        *(float4*)(out + (size_t)(row0 + ty * 4 + i) * K + col0 + tx * 4) = r;
    }
}

// ---------------------------------------------------------------------------
// RoPE3D (in place). One thread handles one (token, head, axis) chunk of 16.
// ---------------------------------------------------------------------------
__global__ void rope3d_kernel(float* __restrict__ X, const int* __restrict__ pos)
{
    int idx = blockIdx.x * blockDim.x + threadIdx.x;  // TT*HH*3 = 196608
    if (idx >= TT * HH * 3) return;
    int a = idx % 3;
    int h = (idx / 3) % HH;
    int t = idx / (3 * HH);

    float p = (float)pos[t * 3 + a];
    float* x = X + (size_t)t * CC + h * HD + a * 16;

    float v[16];
#pragma unroll
    for (int c = 0; c < 4; c++) {
        float4 f = ((const float4*)x)[c];
        v[c * 4 + 0] = f.x; v[c * 4 + 1] = f.y; v[c * 4 + 2] = f.z; v[c * 4 + 3] = f.w;
    }

    const float LOG2_100 = 6.643856189774724f;
#pragma unroll
    for (int j = 0; j < 8; j++) {
        float inv = exp2f(-(float)j * 0.125f * LOG2_100);  // 100^(-j/8)
        float ang = p * inv;
        float sn, cs;
        sincosf(ang, &sn, &cs);
        float x1 = v[j], x2 = v[j + 8];
        v[j]     = x1 * cs - x2 * sn;
        v[j + 8] = x2 * cs + x1 * sn;
    }

#pragma unroll
    for (int c = 0; c < 4; c++) {
        float4 f;
        f.x = v[c * 4 + 0]; f.y = v[c * 4 + 1]; f.z = v[c * 4 + 2]; f.w = v[c * 4 + 3];
        ((float4*)x)[c] = f;
    }
}

// ---------------------------------------------------------------------------
// Attention: grid (N/128, H, B), 128 threads; thread = one query row.
// Packed f32x2 everywhere: q, o as 24 packed regs each; dot uses 2 acc chains.
// Online softmax with lazy max-rescale.
// ---------------------------------------------------------------------------
__global__ void attn_kernel(const float* __restrict__ Q,
                            const float* __restrict__ K,
                            const float* __restrict__ V,
                            float* __restrict__ X)
{
    __shared__ float4 Ks[64 * 12];
    __shared__ float4 Vs[64 * 12];

    int tid = threadIdx.x;                 // 0..127
    int b = blockIdx.z;
    int h = blockIdx.y;
    int qi = blockIdx.x * 128 + tid;       // query index within segment
    int t = b * NN + qi;

    // Load q row (48 floats) into 24 packed regs
    const float* qptr = Q + (size_t)t * CC + h * HD;
    u64 q2[24];
#pragma unroll
    for (int c = 0; c < 12; c++) {
        ulonglong2 f = ((const ulonglong2*)qptr)[c];
        q2[2 * c + 0] = f.x;
        q2[2 * c + 1] = f.y;
    }

    float m = -1e30f, l = 0.f;
    u64 o2[24];
#pragma unroll
    for (int d = 0; d < 24; d++) o2[d] = 0ull;

    const size_t seg_base = (size_t)b * NN;

    for (int kt = 0; kt < NN; kt += 64) {
        __syncthreads();
        // Stage K and V tiles: 64 rows x 12 float4 each
        for (int e = tid; e < 768; e += 128) {
            int r = e / 12, c = e % 12;
            size_t off = (seg_base + kt + r) * CC + h * HD;
            Ks[e] = ((const float4*)(K + off))[c];
            Vs[e] = ((const float4*)(V + off))[c];
        }
        __syncthreads();

        for (int j = 0; j < 64; j++) {
            // s = q . k_j  — two independent packed accumulator chains
            const ulonglong2* kr = (const ulonglong2*)&Ks[j * 12];
            u64 acc0 = 0ull, acc1 = 0ull;
#pragma unroll
            for (int c = 0; c < 12; c++) {
                ulonglong2 kk = kr[c];
                acc0 = ffma2(q2[2 * c + 0], kk.x, acc0);
                acc1 = ffma2(q2[2 * c + 1], kk.y, acc1);
            }
            float2 aa = unpack2(fadd2(acc0, acc1));
            float s = (aa.x + aa.y) * SCALE;

            if (s > m) {                       // rare: new running max
                float alpha = __expf(m - s);
                l *= alpha;
                u64 al2 = pack2(alpha, alpha);
#pragma unroll
                for (int d = 0; d < 24; d++) o2[d] = fmul2(o2[d], al2);
                m = s;
            }
            float p = __expf(s - m);
            l += p;
            u64 p2 = pack2(p, p);
            const ulonglong2* vr = (const ulonglong2*)&Vs[j * 12];
#pragma unroll
            for (int c = 0; c < 12; c++) {
                ulonglong2 vv = vr[c];
                o2[2 * c + 0] = ffma2(p2, vv.x, o2[2 * c + 0]);
                o2[2 * c + 1] = ffma2(p2, vv.y, o2[2 * c + 1]);
            }
        }
    }

    float inv_l = 1.f / l;
    u64 il2 = pack2(inv_l, inv_l);
    float* xptr = X + (size_t)t * CC + h * HD;
#pragma unroll
    for (int c = 0; c < 12; c++) {
        ulonglong2 f;
        f.x = fmul2(o2[2 * c + 0], il2);
        f.y = fmul2(o2[2 * c + 1], il2);
        ((ulonglong2*)xptr)[c] = f;
    }
}

// ---------------------------------------------------------------------------
// Launch
// ---------------------------------------------------------------------------
extern "C" void kernel_launch(void* const* d_in, const int* in_sizes, int n_in,
                              void* d_out, int out_size)
{
    const float* query = (const float*)d_in[0];
    const float* key   = (const float*)d_in[1];
    const float* value = (const float*)d_in[2];
    const float* Wq = (const float*)d_in[3];
    const float* bq = (const float*)d_in[4];
    const float* Wk = (const float*)d_in[5];
    const float* bk = (const float*)d_in[6];
    const float* Wv = (const float*)d_in[7];
    const float* bv = (const float*)d_in[8];
    const float* Wo = (const float*)d_in[9];
    const float* bo = (const float*)d_in[10];
    const int* qpos = (const int*)d_in[11];
    const int* kpos = (const int*)d_in[12];
    float* out = (float*)d_out;

    float *pQ, *pK, *pV, *pX;
    cudaGetSymbolAddress((void**)&pQ, g_Q);
    cudaGetSymbolAddress((void**)&pK, g_K);
    cudaGetSymbolAddress((void**)&pV, g_V);
    cudaGetSymbolAddress((void**)&pX, g_X);

    dim3 ggrid(CC / 64, TT / 64);   // (6, 128)

    gemm_nt_bias<<<ggrid, 256>>>(query, Wq, bq, pQ);
    gemm_nt_bias<<<ggrid, 256>>>(key,   Wk, bk, pK);
    gemm_nt_bias<<<ggrid, 256>>>(value, Wv, bv, pV);

    int rope_threads = TT * HH * 3;
    rope3d_kernel<<<(rope_threads + 255) / 256, 256>>>(pQ, qpos);
    rope3d_kernel<<<(rope_threads + 255) / 256, 256>>>(pK, kpos);

    attn_kernel<<<dim3(NN / 128, HH, BB), 128>>>(pQ, pK, pV, pX);

    gemm_nt_bias<<<ggrid, 256>>>(pX, Wo, bo, out);
}

// round 3
// speedup vs baseline: 3.1838x; 3.1838x over previous
#include <cuda_runtime.h>
#include <cuda_fp16.h>
#include <math.h>

// Problem constants
#define BB 4
#define NN 2048
#define CC 384
#define HH 8
#define HD 48
#define TT (BB * NN)          // 8192 tokens
#define SCALE 0.14433756729740645f  // 1/sqrt(48)

// Scratch (static device globals — no runtime allocation)
__device__ float g_Q[TT * CC];
__device__ float g_K[TT * CC];
__device__ float g_V[TT * CC];
__device__ float g_X[TT * CC];
__device__ __half g_Qh[TT * CC];   // head-major: [B][H][N][HD]
__device__ __half g_Kh[TT * CC];
__device__ __half g_Vh[TT * CC];

// ---------------------------------------------------------------------------
// GEMM (fp32, validated in R1): out[m][n] = sum_k A[m][k] * W[n][k] + bias[n]
// ---------------------------------------------------------------------------
__global__ void gemm_nt_bias(const float* __restrict__ A,
                             const float* __restrict__ W,
                             const float* __restrict__ bias,
                             float* __restrict__ out)
{
    const int K = CC;
    __shared__ float As[16][68];
    __shared__ float Ws[16][68];

    int tid = threadIdx.x;
    int tx = tid & 15;
    int ty = tid >> 4;
    int row0 = blockIdx.y * 64;
    int col0 = blockIdx.x * 64;
    int lr = tid >> 2;
    int lk = (tid & 3) << 2;

    float acc[4][4];
#pragma unroll
    for (int i = 0; i < 4; i++)
#pragma unroll
        for (int j = 0; j < 4; j++) acc[i][j] = 0.f;

    for (int k0 = 0; k0 < K; k0 += 16) {
        float4 a = *(const float4*)(A + (size_t)(row0 + lr) * K + k0 + lk);
        float4 w = *(const float4*)(W + (size_t)(col0 + lr) * K + k0 + lk);
        __syncthreads();
        As[lk + 0][lr] = a.x; As[lk + 1][lr] = a.y;
        As[lk + 2][lr] = a.z; As[lk + 3][lr] = a.w;
        Ws[lk + 0][lr] = w.x; Ws[lk + 1][lr] = w.y;
        Ws[lk + 2][lr] = w.z; Ws[lk + 3][lr] = w.w;
        __syncthreads();

#pragma unroll
        for (int kk = 0; kk < 16; kk++) {
            float4 av = *(const float4*)&As[kk][ty * 4];
            float4 wv = *(const float4*)&Ws[kk][tx * 4];
            float ar[4] = {av.x, av.y, av.z, av.w};
            float wr[4] = {wv.x, wv.y, wv.z, wv.w};
#pragma unroll
            for (int i = 0; i < 4; i++)
#pragma unroll
                for (int j = 0; j < 4; j++)
                    acc[i][j] += ar[i] * wr[j];
        }
    }

    float4 bv = *(const float4*)(bias + col0 + tx * 4);
    float bb[4] = {bv.x, bv.y, bv.z, bv.w};
#pragma unroll
    for (int i = 0; i < 4; i++) {
        float4 r;
        r.x = acc[i][0] + bb[0];
        r.y = acc[i][1] + bb[1];
        r.z = acc[i][2] + bb[2];
        r.w = acc[i][3] + bb[3];
        *(float4*)(out + (size_t)(row0 + ty * 4 + i) * K + col0 + tx * 4) = r;
    }
}

// ---------------------------------------------------------------------------
// RoPE3D + fp16 convert + transpose to head-major [B][H][N][HD].
// One thread per (token, head, axis-chunk-of-16). mult folds the softmax
// scale into Q (mult=SCALE) and is 1.0 for K.
// ---------------------------------------------------------------------------
__global__ void rope_cvt(const float* __restrict__ X, const int* __restrict__ pos,
                         __half* __restrict__ dst, float mult)
{
    int idx = blockIdx.x * blockDim.x + threadIdx.x;
    if (idx >= TT * HH * 3) return;
    int a = idx % 3;
    int h = (idx / 3) % HH;
    int t = idx / (3 * HH);
    int b = t / NN, n = t % NN;

    float p = (float)pos[t * 3 + a];
    const float* x = X + (size_t)t * CC + h * HD + a * 16;

    float v[16];
#pragma unroll
    for (int c = 0; c < 4; c++) {
        float4 f = ((const float4*)x)[c];
        v[c * 4 + 0] = f.x; v[c * 4 + 1] = f.y; v[c * 4 + 2] = f.z; v[c * 4 + 3] = f.w;
    }

    const float LOG2_100 = 6.643856189774724f;
#pragma unroll
    for (int j = 0; j < 8; j++) {
        float inv = exp2f(-(float)j * 0.125f * LOG2_100);
        float ang = p * inv;
        float sn, cs;
        sincosf(ang, &sn, &cs);
        float x1 = v[j], x2 = v[j + 8];
        v[j]     = x1 * cs - x2 * sn;
        v[j + 8] = x2 * cs + x1 * sn;
    }

    unsigned int r[8];
#pragma unroll
    for (int i = 0; i < 8; i++) {
        __half2 h2 = __floats2half2_rn(v[2 * i] * mult, v[2 * i + 1] * mult);
        r[i] = *reinterpret_cast<unsigned int*>(&h2);
    }
    __half* d = dst + ((size_t)(b * HH + h) * NN + n) * HD + a * 16;
    uint4 o0 = {r[0], r[1], r[2], r[3]};
    uint4 o1 = {r[4], r[5], r[6], r[7]};
    ((uint4*)d)[0] = o0;
    ((uint4*)d)[1] = o1;
}

// V: fp16 convert + transpose to head-major (no rope). Thread per (token, head).
__global__ void v_cvt(const float* __restrict__ V, __half* __restrict__ dst)
{
    int idx = blockIdx.x * blockDim.x + threadIdx.x;
    if (idx >= TT * HH) return;
    int h = idx % HH;
    int t = idx / HH;
    int b = t / NN, n = t % NN;

    const float* src = V + (size_t)t * CC + h * HD;
    __half* d = dst + ((size_t)(b * HH + h) * NN + n) * HD;
#pragma unroll
    for (int c = 0; c < 6; c++) {
        float4 f0 = ((const float4*)src)[2 * c];
        float4 f1 = ((const float4*)src)[2 * c + 1];
        __half2 h0 = __floats2half2_rn(f0.x, f0.y);
        __half2 h1 = __floats2half2_rn(f0.z, f0.w);
        __half2 h2 = __floats2half2_rn(f1.x, f1.y);
        __half2 h3 = __floats2half2_rn(f1.z, f1.w);
        uint4 o;
        o.x = *reinterpret_cast<unsigned int*>(&h0);
        o.y = *reinterpret_cast<unsigned int*>(&h1);
        o.z = *reinterpret_cast<unsigned int*>(&h2);
        o.w = *reinterpret_cast<unsigned int*>(&h3);
        ((uint4*)d)[c] = o;
    }
}

// ---------------------------------------------------------------------------
// Tensor-core flash attention.
// Block: 64 queries, 4 warps (warp = 16 query rows). Key tiles of 64.
// mma.m16n8k16 f16->f32; S-accum reused as P A-fragment (FA2 trick).
// ---------------------------------------------------------------------------
#define ATS 56   // shared row stride in halfs (112B: conflict-free ldmatrix)

__device__ __forceinline__ void ldsm_x4(unsigned int addr, unsigned int& r0,
                                        unsigned int& r1, unsigned int& r2, unsigned int& r3)
{
    asm volatile("ldmatrix.sync.aligned.m8n8.x4.shared.b16 {%0,%1,%2,%3}, [%4];"
                 : "=r"(r0), "=r"(r1), "=r"(r2), "=r"(r3) : "r"(addr));
}
__device__ __forceinline__ void ldsm_x4_t(unsigned int addr, unsigned int& r0,
                                          unsigned int& r1, unsigned int& r2, unsigned int& r3)
{
    asm volatile("ldmatrix.sync.aligned.m8n8.x4.trans.shared.b16 {%0,%1,%2,%3}, [%4];"
                 : "=r"(r0), "=r"(r1), "=r"(r2), "=r"(r3) : "r"(addr));
}
__device__ __forceinline__ void mma16816(float* c, unsigned int a0, unsigned int a1,
                                         unsigned int a2, unsigned int a3,
                                         unsigned int b0, unsigned int b1)
{
    asm volatile("mma.sync.aligned.m16n8k16.row.col.f32.f16.f16.f32 "
                 "{%0,%1,%2,%3}, {%4,%5,%6,%7}, {%8,%9}, {%0,%1,%2,%3};"
                 : "+f"(c[0]), "+f"(c[1]), "+f"(c[2]), "+f"(c[3])
                 : "r"(a0), "r"(a1), "r"(a2), "r"(a3), "r"(b0), "r"(b1));
}
__device__ __forceinline__ unsigned int packh2(float x, float y)
{
    __half2 h = __floats2half2_rn(x, y);
    return *reinterpret_cast<unsigned int*>(&h);
}

__global__ __launch_bounds__(128) void attn_mma(const __half* __restrict__ Qh,
                                                const __half* __restrict__ Kh,
                                                const __half* __restrict__ Vh,
                                                float* __restrict__ X)
{
    __shared__ __half Qs[64 * ATS];
    __shared__ __half Ks[64 * ATS];
    __shared__ __half Vs[64 * ATS];

    int tid = threadIdx.x, lane = tid & 31, w = tid >> 5;
    int b = blockIdx.z, h = blockIdx.y;
    const size_t hb = ((size_t)(b * HH + h)) * NN * HD;
    int q0 = blockIdx.x * 64;

    // Stage Q tile (64 x 48 halfs)
    for (int e = tid; e < 384; e += 128) {
        int r = e / 6, c = e % 6;
        *(uint4*)&Qs[r * ATS + c * 8] = *(const uint4*)(Qh + hb + (size_t)(q0 + r) * HD + c * 8);
    }
    __syncthreads();

    unsigned int qs_base = (unsigned int)__cvta_generic_to_shared(Qs);
    unsigned int ks_base = (unsigned int)__cvta_generic_to_shared(Ks);
    unsigned int vs_base = (unsigned int)__cvta_generic_to_shared(Vs);

    // Q A-fragments (persist across all key tiles)
    unsigned int qa[3][4];
    {
        int arow = w * 16 + (lane & 15);
        int acol = (lane >> 4) * 8;
#pragma unroll
        for (int k = 0; k < 3; k++) {
            unsigned int addr = qs_base + (unsigned int)((arow * ATS + k * 16 + acol) * 2);
            ldsm_x4(addr, qa[k][0], qa[k][1], qa[k][2], qa[k][3]);
        }
    }

    float o[6][4];
#pragma unroll
    for (int n = 0; n < 6; n++)
#pragma unroll
        for (int j = 0; j < 4; j++) o[n][j] = 0.f;
    float m0 = -1e30f, m1 = -1e30f, l0 = 0.f, l1 = 0.f;

    // ldmatrix per-lane offsets (row*ATS + col), in halfs
    int kb_off = ((lane & 7) + ((lane >> 4) & 1) * 8) * ATS + ((lane >> 3) & 1) * 8;
    int vb_off = ((lane & 7) + ((lane >> 3) & 1) * 8) * ATS + ((lane >> 4) & 1) * 8;

    for (int kt0 = 0; kt0 < NN; kt0 += 64) {
        __syncthreads();
        for (int e = tid; e < 384; e += 128) {
            int r = e / 6, c = e % 6;
            size_t g = hb + (size_t)(kt0 + r) * HD + c * 8;
            *(uint4*)&Ks[r * ATS + c * 8] = *(const uint4*)(Kh + g);
            *(uint4*)&Vs[r * ATS + c * 8] = *(const uint4*)(Vh + g);
        }
        __syncthreads();

        // S = Q K^T (scale pre-folded into Q)
        float s[8][4];
#pragma unroll
        for (int n = 0; n < 8; n++)
#pragma unroll
            for (int j = 0; j < 4; j++) s[n][j] = 0.f;

#pragma unroll
        for (int np = 0; np < 4; np++) {
#pragma unroll
            for (int k = 0; k < 3; k++) {
                unsigned int addr = ks_base +
                    (unsigned int)(((np * 16) * ATS + k * 16 + kb_off) * 2);
                unsigned int b0, b1, b2, b3;
                ldsm_x4(addr, b0, b1, b2, b3);
                mma16816(s[2 * np],     qa[k][0], qa[k][1], qa[k][2], qa[k][3], b0, b1);
                mma16816(s[2 * np + 1], qa[k][0], qa[k][1], qa[k][2], qa[k][3], b2, b3);
            }
        }

        // Online softmax (rows r0 = lane/4, r1 = r0+8; quad holds the row)
        float tm0 = s[0][0], tm1 = s[0][2];
#pragma unroll
        for (int n = 0; n < 8; n++) {
            tm0 = fmaxf(tm0, fmaxf(s[n][0], s[n][1]));
            tm1 = fmaxf(tm1, fmaxf(s[n][2], s[n][3]));
        }
        tm0 = fmaxf(tm0, __shfl_xor_sync(0xffffffffu, tm0, 1));
        tm0 = fmaxf(tm0, __shfl_xor_sync(0xffffffffu, tm0, 2));
        tm1 = fmaxf(tm1, __shfl_xor_sync(0xffffffffu, tm1, 1));
        tm1 = fmaxf(tm1, __shfl_xor_sync(0xffffffffu, tm1, 2));

        float nm0 = fmaxf(m0, tm0), nm1 = fmaxf(m1, tm1);
        float al0 = __expf(m0 - nm0), al1 = __expf(m1 - nm1);
        m0 = nm0; m1 = nm1;
        l0 *= al0; l1 *= al1;
#pragma unroll
        for (int n = 0; n < 6; n++) {
            o[n][0] *= al0; o[n][1] *= al0;
            o[n][2] *= al1; o[n][3] *= al1;
        }
#pragma unroll
        for (int n = 0; n < 8; n++) {
            s[n][0] = __expf(s[n][0] - m0);
            s[n][1] = __expf(s[n][1] - m0);
            s[n][2] = __expf(s[n][2] - m1);
            s[n][3] = __expf(s[n][3] - m1);
            l0 += s[n][0] + s[n][1];
            l1 += s[n][2] + s[n][3];
        }

        // O += P V  (S accum layout == A fragment layout)
#pragma unroll
        for (int kt = 0; kt < 4; kt++) {
            unsigned int a0 = packh2(s[2 * kt][0],     s[2 * kt][1]);
            unsigned int a1 = packh2(s[2 * kt][2],     s[2 * kt][3]);
            unsigned int a2 = packh2(s[2 * kt + 1][0], s[2 * kt + 1][1]);
            unsigned int a3 = packh2(s[2 * kt + 1][2], s[2 * kt + 1][3]);
#pragma unroll
            for (int np = 0; np < 3; np++) {
                unsigned int addr = vs_base +
                    (unsigned int)(((kt * 16) * ATS + np * 16 + vb_off) * 2);
                unsigned int b0, b1, b2, b3;
                ldsm_x4_t(addr, b0, b1, b2, b3);
                mma16816(o[2 * np],     a0, a1, a2, a3, b0, b1);
                mma16816(o[2 * np + 1], a0, a1, a2, a3, b2, b3);
            }
        }
    }

    // Final normalize + write (token-major fp32 for the output GEMM)
    l0 += __shfl_xor_sync(0xffffffffu, l0, 1);
    l0 += __shfl_xor_sync(0xffffffffu, l0, 2);
    l1 += __shfl_xor_sync(0xffffffffu, l1, 1);
    l1 += __shfl_xor_sync(0xffffffffu, l1, 2);
    float i0 = 1.f / l0, i1 = 1.f / l1;

    int r0 = q0 + w * 16 + (lane >> 2);
    int cbase = h * HD + (lane & 3) * 2;
#pragma unroll
    for (int n = 0; n < 6; n++) {
        float2 f0; f0.x = o[n][0] * i0; f0.y = o[n][1] * i0;
        float2 f1; f1.x = o[n][2] * i1; f1.y = o[n][3] * i1;
        *(float2*)&X[(size_t)(b * NN + r0) * CC + cbase + n * 8] = f0;
        *(float2*)&X[(size_t)(b * NN + r0 + 8) * CC + cbase + n * 8] = f1;
    }
}

// ---------------------------------------------------------------------------
// Launch
// ---------------------------------------------------------------------------
extern "C" void kernel_launch(void* const* d_in, const int* in_sizes, int n_in,
                              void* d_out, int out_size)
{
    const float* query = (const float*)d_in[0];
    const float* key   = (const float*)d_in[1];
    const float* value = (const float*)d_in[2];
    const float* Wq = (const float*)d_in[3];
    const float* bq = (const float*)d_in[4];
    const float* Wk = (const float*)d_in[5];
    const float* bk = (const float*)d_in[6];
    const float* Wv = (const float*)d_in[7];
    const float* bv = (const float*)d_in[8];
    const float* Wo = (const float*)d_in[9];
    const float* bo = (const float*)d_in[10];
    const int* qpos = (const int*)d_in[11];
    const int* kpos = (const int*)d_in[12];
    float* out = (float*)d_out;

    float *pQ, *pK, *pV, *pX;
    __half *pQh, *pKh, *pVh;
    cudaGetSymbolAddress((void**)&pQ, g_Q);
    cudaGetSymbolAddress((void**)&pK, g_K);
    cudaGetSymbolAddress((void**)&pV, g_V);
    cudaGetSymbolAddress((void**)&pX, g_X);
    cudaGetSymbolAddress((void**)&pQh, g_Qh);
    cudaGetSymbolAddress((void**)&pKh, g_Kh);
    cudaGetSymbolAddress((void**)&pVh, g_Vh);

    dim3 ggrid(CC / 64, TT / 64);   // (6, 128)

    gemm_nt_bias<<<ggrid, 256>>>(query, Wq, bq, pQ);
    gemm_nt_bias<<<ggrid, 256>>>(key,   Wk, bk, pK);
    gemm_nt_bias<<<ggrid, 256>>>(value, Wv, bv, pV);

    int rope_threads = TT * HH * 3;
    rope_cvt<<<(rope_threads + 255) / 256, 256>>>(pQ, qpos, pQh, SCALE);
    rope_cvt<<<(rope_threads + 255) / 256, 256>>>(pK, kpos, pKh, 1.0f);
    v_cvt<<<(TT * HH + 255) / 256, 256>>>(pV, pVh);

    attn_mma<<<dim3(NN / 64, HH, BB), 128>>>(pQh, pKh, pVh, pX);

    gemm_nt_bias<<<ggrid, 256>>>(pX, Wo, bo, out);
}